// round 1
// baseline (speedup 1.0000x reference)
#include <cuda_runtime.h>
#include <cuda_bf16.h>
#include <math_constants.h>

#define ENC_DIM 256
#define INT_DIM 256
#define ROWS 64           // t-rows per block in scores kernel
#define XS_PITCH 66       // padded smem pitch (2-way store conflict, 8B aligned pairs)

// Scratch (allocation-free rule: __device__ globals)
__device__ float g_dp[64 * INT_DIM];        // dec_proj [B, I]
__device__ float g_scores[64 * 2048];       // scores   [B, T]

// ---------------------------------------------------------------------------
// packed fp32x2 FMA (sm_103a: doubles FFMA issue rate vs 3-reg FFMA)
// ---------------------------------------------------------------------------
__device__ __forceinline__ float2 ffma2(float2 a, float2 b, float2 c) {
    float2 d;
    asm("fma.rn.f32x2 %0, %1, %2, %3;"
        : "=l"(reinterpret_cast<unsigned long long&>(d))
        : "l"(reinterpret_cast<unsigned long long&>(a)),
          "l"(reinterpret_cast<unsigned long long&>(b)),
          "l"(reinterpret_cast<unsigned long long&>(c)));
    return d;
}

// ---------------------------------------------------------------------------
// K1: dec_proj[b,i] = sum_k w2[i,k] * dec[b,k]
// ---------------------------------------------------------------------------
__global__ void decproj_kernel(const float* __restrict__ dec,
                               const float* __restrict__ w2,
                               float* __restrict__ dp) {
    __shared__ float ds[ENC_DIM];
    const int b = blockIdx.x;
    const int i = threadIdx.x;
    ds[i] = dec[b * ENC_DIM + i];
    __syncthreads();
    const float* w = w2 + i * ENC_DIM;
    float acc = 0.f;
#pragma unroll 8
    for (int k = 0; k < ENC_DIM; ++k) acc = fmaf(__ldg(w + k), ds[k], acc);
    dp[b * INT_DIM + i] = acc;
}

// ---------------------------------------------------------------------------
// K2: fused scores. Block = 64 rows (b,t) x 256 hidden.
//   h[r,i] = tanh( sum_k X[r,k]*w1[i,k] + dp[b,i] );  score[r] = sum_i v[i]*h[r,i]
// Thread (tid): i in {tid&63 + 64j, j=0..3}, rows [16*(tid>>6), +16) as 8 f32x2 pairs.
// ---------------------------------------------------------------------------
__global__ void __launch_bounds__(256, 2)
scores_kernel(const float* __restrict__ enc,
              const float* __restrict__ w1,
              const float* __restrict__ dp,
              const float* __restrict__ v,
              float* __restrict__ scores,
              int T) {
    extern __shared__ float xs[];          // [256][XS_PITCH] transposed X tile
    __shared__ float ssc[ROWS];

    const int tid = threadIdx.x;
    const long long row0 = (long long)blockIdx.x * ROWS;
    const float* src = enc + row0 * ENC_DIM;

    // Load X tile transposed: xs[k][r] = X[r][k]. Global coalesced.
#pragma unroll 8
    for (int it = 0; it < ROWS; ++it)
        xs[tid * XS_PITCH + it] = src[it * ENC_DIM + tid];

    if (tid < ROWS) ssc[tid] = 0.f;
    __syncthreads();

    const int i0 = tid & 63;
    const int rb = (tid >> 6) * 16;
    const float* w1p = w1 + i0 * ENC_DIM;

    float2 acc[4][8];
#pragma unroll
    for (int j = 0; j < 4; ++j)
#pragma unroll
        for (int p = 0; p < 8; ++p) acc[j][p] = make_float2(0.f, 0.f);

#pragma unroll 2
    for (int k = 0; k < ENC_DIM; ++k) {
        float2 wp[4];
#pragma unroll
        for (int j = 0; j < 4; ++j) {
            float w = __ldg(w1p + j * 64 * ENC_DIM + k);
            wp[j] = make_float2(w, w);
        }
        const float2* xp = reinterpret_cast<const float2*>(xs + k * XS_PITCH + rb);
#pragma unroll
        for (int p = 0; p < 8; ++p) {
            float2 x = xp[p];             // warp-uniform address -> broadcast
#pragma unroll
            for (int j = 0; j < 4; ++j) acc[j][p] = ffma2(x, wp[j], acc[j][p]);
        }
    }

    // Epilogue: + dec_proj, tanh, * v[i], reduce over i.
    const int b = (int)(row0 / T);
    float pr[16];
#pragma unroll
    for (int r = 0; r < 16; ++r) pr[r] = 0.f;

#pragma unroll
    for (int j = 0; j < 4; ++j) {
        const int i = i0 + j * 64;
        const float d  = dp[b * INT_DIM + i];
        const float vv = __ldg(v + i);
#pragma unroll
        for (int p = 0; p < 8; ++p) {
            pr[2 * p]     = fmaf(vv, tanhf(acc[j][p].x + d), pr[2 * p]);
            pr[2 * p + 1] = fmaf(vv, tanhf(acc[j][p].y + d), pr[2 * p + 1]);
        }
    }
#pragma unroll
    for (int r = 0; r < 16; ++r) atomicAdd(&ssc[rb + r], pr[r]);
    __syncthreads();

    if (tid < ROWS) scores[row0 + tid] = ssc[tid];
}

// ---------------------------------------------------------------------------
// K3: per-batch softmax over T, write probs, and context = sum_t p_t * X[t,:]
// out layout: [0, B*256) context ; [B*256, B*256 + B*T) probs
// ---------------------------------------------------------------------------
__global__ void softmax_ctx_kernel(const float* __restrict__ enc,
                                   const float* __restrict__ scores,
                                   float* __restrict__ out,
                                   int B, int T) {
    extern __shared__ float ss[];          // T floats
    __shared__ float red[8];
    const int b = blockIdx.x;
    const int tid = threadIdx.x;
    const int lane = tid & 31, wid = tid >> 5;

    for (int t = tid; t < T; t += 256) ss[t] = scores[b * T + t];
    __syncthreads();

    // block max
    float m = -CUDART_INF_F;
    for (int t = tid; t < T; t += 256) m = fmaxf(m, ss[t]);
#pragma unroll
    for (int o = 16; o; o >>= 1) m = fmaxf(m, __shfl_xor_sync(0xffffffffu, m, o));
    if (lane == 0) red[wid] = m;
    __syncthreads();
    if (tid == 0) {
        float mm = red[0];
#pragma unroll
        for (int w = 1; w < 8; ++w) mm = fmaxf(mm, red[w]);
        red[0] = mm;
    }
    __syncthreads();
    m = red[0];
    __syncthreads();

    // block sum of exp
    float z = 0.f;
    for (int t = tid; t < T; t += 256) z += expf(ss[t] - m);
#pragma unroll
    for (int o = 16; o; o >>= 1) z += __shfl_xor_sync(0xffffffffu, z, o);
    if (lane == 0) red[wid] = z;
    __syncthreads();
    if (tid == 0) {
        float zz = 0.f;
#pragma unroll
        for (int w = 0; w < 8; ++w) zz += red[w];
        red[0] = zz;
    }
    __syncthreads();
    const float inv = 1.f / red[0];

    // probs out + keep p in smem
    float* probs = out + (long long)B * ENC_DIM;
    for (int t = tid; t < T; t += 256) {
        float p = expf(ss[t] - m) * inv;
        ss[t] = p;
        probs[(long long)b * T + t] = p;
    }
    __syncthreads();

    // context: thread owns one e-dim, coalesced stream over encoder rows
    float c = 0.f;
    const float* e = enc + (long long)b * T * ENC_DIM + tid;
#pragma unroll 8
    for (int t = 0; t < T; ++t) c = fmaf(ss[t], __ldg(e + (long long)t * ENC_DIM), c);
    out[b * ENC_DIM + tid] = c;
}

// ---------------------------------------------------------------------------
extern "C" void kernel_launch(void* const* d_in, const int* in_sizes, int n_in,
                              void* d_out, int out_size) {
    const float* enc = (const float*)d_in[0];   // [B,T,256]
    const float* dec = (const float*)d_in[1];   // [B,256]
    const float* w1  = (const float*)d_in[2];   // [256,256]
    const float* w2  = (const float*)d_in[3];   // [256,256]
    const float* v   = (const float*)d_in[4];   // [1,256]
    float* out = (float*)d_out;

    const int B = in_sizes[1] / ENC_DIM;                 // 64
    const int T = in_sizes[0] / (B * ENC_DIM);           // 2048

    float* dp_ptr;      cudaGetSymbolAddress((void**)&dp_ptr, g_dp);
    float* scores_ptr;  cudaGetSymbolAddress((void**)&scores_ptr, g_scores);

    static const int xs_bytes = 256 * XS_PITCH * (int)sizeof(float);   // 67584
    cudaFuncSetAttribute(scores_kernel,
                         cudaFuncAttributeMaxDynamicSharedMemorySize, xs_bytes);

    decproj_kernel<<<B, 256>>>(dec, w2, dp_ptr);
    scores_kernel<<<(B * T) / ROWS, 256, xs_bytes>>>(enc, w1, dp_ptr, v, scores_ptr, T);
    softmax_ctx_kernel<<<B, 256, T * (int)sizeof(float)>>>(enc, scores_ptr, out, B, T);
}

// round 2
// speedup vs baseline: 4.5338x; 4.5338x over previous
#include <cuda_runtime.h>
#include <cuda_bf16.h>
#include <math_constants.h>

#define ENC_DIM 256
#define INT_DIM 256
#define ROWS 64           // t-rows per block in scores kernel
#define XS_PITCH 66       // padded smem pitch (2-way store conflict, 8B aligned pairs)

// Scratch (allocation-free rule: __device__ globals)
__device__ float g_dp[64 * INT_DIM];        // dec_proj [B, I]
__device__ float g_scores[64 * 2048];       // scores   [B, T]
__device__ float g_w1t[ENC_DIM * INT_DIM];  // w1 transposed: [k][i]
__device__ float g_w2t[ENC_DIM * INT_DIM];  // w2 transposed: [k][i]

// ---------------------------------------------------------------------------
// packed fp32x2 FMA (sm_103a: doubles FFMA issue rate vs 3-reg FFMA)
// ---------------------------------------------------------------------------
__device__ __forceinline__ float2 ffma2(float2 a, float2 b, float2 c) {
    float2 d;
    asm("fma.rn.f32x2 %0, %1, %2, %3;"
        : "=l"(reinterpret_cast<unsigned long long&>(d))
        : "l"(reinterpret_cast<unsigned long long&>(a)),
          "l"(reinterpret_cast<unsigned long long&>(b)),
          "l"(reinterpret_cast<unsigned long long&>(c)));
    return d;
}

// ---------------------------------------------------------------------------
// K0: transpose 256x256 (w[y][x] -> wt[x][y]), grid (8,8,2), block (32,8)
// ---------------------------------------------------------------------------
__global__ void transpose256_kernel(const float* __restrict__ w1,
                                    const float* __restrict__ w2,
                                    float* __restrict__ w1t,
                                    float* __restrict__ w2t) {
    __shared__ float tile[32][33];
    const float* w  = blockIdx.z ? w2  : w1;
    float*       wt = blockIdx.z ? w2t : w1t;
    int x = blockIdx.x * 32 + threadIdx.x;
    int y = blockIdx.y * 32 + threadIdx.y;
#pragma unroll
    for (int dy = 0; dy < 32; dy += 8)
        tile[threadIdx.y + dy][threadIdx.x] = w[(y + dy) * 256 + x];
    __syncthreads();
    x = blockIdx.y * 32 + threadIdx.x;
    y = blockIdx.x * 32 + threadIdx.y;
#pragma unroll
    for (int dy = 0; dy < 32; dy += 8)
        wt[(y + dy) * 256 + x] = tile[threadIdx.x][threadIdx.y + dy];
}

// ---------------------------------------------------------------------------
// K1: dec_proj[b,i] = sum_k w2t[k,i] * dec[b,k]   (coalesced in i)
// ---------------------------------------------------------------------------
__global__ void decproj_kernel(const float* __restrict__ dec,
                               const float* __restrict__ w2t,
                               float* __restrict__ dp) {
    __shared__ float ds[ENC_DIM];
    const int b = blockIdx.x;
    const int i = threadIdx.x;
    ds[i] = dec[b * ENC_DIM + i];
    __syncthreads();
    float acc = 0.f;
#pragma unroll 8
    for (int k = 0; k < ENC_DIM; ++k)
        acc = fmaf(__ldg(w2t + k * INT_DIM + i), ds[k], acc);
    dp[b * INT_DIM + i] = acc;
}

// ---------------------------------------------------------------------------
// K2: fused scores. Block = 64 rows (b,t) x 256 hidden.
//   h[r,i] = tanh( sum_k X[r,k]*w1[i,k] + dp[b,i] );  score[r] = sum_i v[i]*h[r,i]
// Thread: i in {tid&63 + 64j}, rows [16*(tid>>6), +16) as 8 f32x2 pairs.
// w1t[k][i] loads are lane-consecutive -> 1 line per warp-LDG.
// ---------------------------------------------------------------------------
__global__ void __launch_bounds__(256, 2)
scores_kernel(const float* __restrict__ enc,
              const float* __restrict__ w1t,
              const float* __restrict__ dp,
              const float* __restrict__ v,
              float* __restrict__ scores,
              int T) {
    extern __shared__ float xs[];          // [256][XS_PITCH] transposed X tile
    __shared__ float ssc[ROWS];

    const int tid = threadIdx.x;
    const long long row0 = (long long)blockIdx.x * ROWS;
    const float* src = enc + row0 * ENC_DIM;

    // Load X tile transposed: xs[k][r] = X[r][k]. Global coalesced.
#pragma unroll 8
    for (int it = 0; it < ROWS; ++it)
        xs[tid * XS_PITCH + it] = src[it * ENC_DIM + tid];

    if (tid < ROWS) ssc[tid] = 0.f;
    __syncthreads();

    const int i0 = tid & 63;
    const int rb = (tid >> 6) * 16;

    float2 acc[4][8];
#pragma unroll
    for (int j = 0; j < 4; ++j)
#pragma unroll
        for (int p = 0; p < 8; ++p) acc[j][p] = make_float2(0.f, 0.f);

#pragma unroll 2
    for (int k = 0; k < ENC_DIM; ++k) {
        float2 wp[4];
        const float* wrow = w1t + k * INT_DIM + i0;
#pragma unroll
        for (int j = 0; j < 4; ++j) {
            float w = __ldg(wrow + j * 64);      // lane-consecutive, coalesced
            wp[j] = make_float2(w, w);
        }
        const float2* xp = reinterpret_cast<const float2*>(xs + k * XS_PITCH + rb);
#pragma unroll
        for (int p = 0; p < 8; ++p) {
            float2 x = xp[p];                    // warp-uniform -> smem broadcast
#pragma unroll
            for (int j = 0; j < 4; ++j) acc[j][p] = ffma2(x, wp[j], acc[j][p]);
        }
    }

    // Epilogue: + dec_proj, tanh, * v[i], reduce over i.
    const int b = (int)(row0 / T);
    float pr[16];
#pragma unroll
    for (int r = 0; r < 16; ++r) pr[r] = 0.f;

#pragma unroll
    for (int j = 0; j < 4; ++j) {
        const int i = i0 + j * 64;
        const float d  = dp[b * INT_DIM + i];
        const float vv = __ldg(v + i);
#pragma unroll
        for (int p = 0; p < 8; ++p) {
            pr[2 * p]     = fmaf(vv, tanhf(acc[j][p].x + d), pr[2 * p]);
            pr[2 * p + 1] = fmaf(vv, tanhf(acc[j][p].y + d), pr[2 * p + 1]);
        }
    }

    // Warp shuffle reduce (all lanes in a warp share rb), then 1 atomic/row/warp.
    const int lane = tid & 31;
#pragma unroll
    for (int r = 0; r < 16; ++r) {
        float s = pr[r];
#pragma unroll
        for (int o = 16; o; o >>= 1) s += __shfl_xor_sync(0xffffffffu, s, o);
        if (lane == 0) atomicAdd(&ssc[rb + r], s);
    }
    __syncthreads();

    if (tid < ROWS) scores[row0 + tid] = ssc[tid];
}

// ---------------------------------------------------------------------------
// K3: per-batch softmax over T, write probs, and context = sum_t p_t * X[t,:]
// out layout: [0, B*256) context ; [B*256, B*256 + B*T) probs
// ---------------------------------------------------------------------------
__global__ void softmax_ctx_kernel(const float* __restrict__ enc,
                                   const float* __restrict__ scores,
                                   float* __restrict__ out,
                                   int B, int T) {
    extern __shared__ float ss[];          // T floats
    __shared__ float red[8];
    const int b = blockIdx.x;
    const int tid = threadIdx.x;
    const int lane = tid & 31, wid = tid >> 5;

    for (int t = tid; t < T; t += 256) ss[t] = scores[b * T + t];
    __syncthreads();

    // block max
    float m = -CUDART_INF_F;
    for (int t = tid; t < T; t += 256) m = fmaxf(m, ss[t]);
#pragma unroll
    for (int o = 16; o; o >>= 1) m = fmaxf(m, __shfl_xor_sync(0xffffffffu, m, o));
    if (lane == 0) red[wid] = m;
    __syncthreads();
    if (tid == 0) {
        float mm = red[0];
#pragma unroll
        for (int w = 1; w < 8; ++w) mm = fmaxf(mm, red[w]);
        red[0] = mm;
    }
    __syncthreads();
    m = red[0];
    __syncthreads();

    // block sum of exp
    float z = 0.f;
    for (int t = tid; t < T; t += 256) z += expf(ss[t] - m);
#pragma unroll
    for (int o = 16; o; o >>= 1) z += __shfl_xor_sync(0xffffffffu, z, o);
    if (lane == 0) red[wid] = z;
    __syncthreads();
    if (tid == 0) {
        float zz = 0.f;
#pragma unroll
        for (int w = 0; w < 8; ++w) zz += red[w];
        red[0] = zz;
    }
    __syncthreads();
    const float inv = 1.f / red[0];

    // probs out + keep p in smem
    float* probs = out + (long long)B * ENC_DIM;
    for (int t = tid; t < T; t += 256) {
        float p = expf(ss[t] - m) * inv;
        ss[t] = p;
        probs[(long long)b * T + t] = p;
    }
    __syncthreads();

    // context: thread owns one e-dim, coalesced stream over encoder rows
    float c = 0.f;
    const float* e = enc + (long long)b * T * ENC_DIM + tid;
#pragma unroll 8
    for (int t = 0; t < T; ++t) c = fmaf(ss[t], __ldg(e + (long long)t * ENC_DIM), c);
    out[b * ENC_DIM + tid] = c;
}

// ---------------------------------------------------------------------------
extern "C" void kernel_launch(void* const* d_in, const int* in_sizes, int n_in,
                              void* d_out, int out_size) {
    const float* enc = (const float*)d_in[0];   // [B,T,256]
    const float* dec = (const float*)d_in[1];   // [B,256]
    const float* w1  = (const float*)d_in[2];   // [256,256]
    const float* w2  = (const float*)d_in[3];   // [256,256]
    const float* v   = (const float*)d_in[4];   // [1,256]
    float* out = (float*)d_out;

    const int B = in_sizes[1] / ENC_DIM;                 // 64
    const int T = in_sizes[0] / (B * ENC_DIM);           // 2048

    float* dp_ptr;      cudaGetSymbolAddress((void**)&dp_ptr, g_dp);
    float* scores_ptr;  cudaGetSymbolAddress((void**)&scores_ptr, g_scores);
    float* w1t_ptr;     cudaGetSymbolAddress((void**)&w1t_ptr, g_w1t);
    float* w2t_ptr;     cudaGetSymbolAddress((void**)&w2t_ptr, g_w2t);

    static const int xs_bytes = 256 * XS_PITCH * (int)sizeof(float);   // 67584
    cudaFuncSetAttribute(scores_kernel,
                         cudaFuncAttributeMaxDynamicSharedMemorySize, xs_bytes);

    transpose256_kernel<<<dim3(8, 8, 2), dim3(32, 8)>>>(w1, w2, w1t_ptr, w2t_ptr);
    decproj_kernel<<<B, 256>>>(dec, w2t_ptr, dp_ptr);
    scores_kernel<<<(B * T) / ROWS, 256, xs_bytes>>>(enc, w1t_ptr, dp_ptr, v, scores_ptr, T);
    softmax_ctx_kernel<<<B, 256, T * (int)sizeof(float)>>>(enc, scores_ptr, out, B, T);
}

// round 3
// speedup vs baseline: 13.2849x; 2.9302x over previous
#include <cuda_runtime.h>
#include <cuda_bf16.h>
#include <math_constants.h>

#define ENC_DIM 256
#define INT_DIM 256
#define MT 128            // rows per block in scores kernel
#define KC 64             // k-chunk staged in smem
#define AP 68             // A smem pitch (words) -> conflict-free frag loads
#define BP 264            // B smem pitch (words) -> conflict-free frag loads

// Scratch (allocation-free rule: __device__ globals)
__device__ float g_dp[64 * INT_DIM];          // dec_proj [B, I]
__device__ float g_scores[64 * 2048];         // scores   [B, T]
__device__ float g_w1t[ENC_DIM * INT_DIM];    // w1 transposed: [k][i]
__device__ float g_w2t[ENC_DIM * INT_DIM];    // w2 transposed: [k][i]
__device__ float g_part[8 * 64 * ENC_DIM];    // context partials [chunk][B][E]

// ---------------------------------------------------------------------------
// helpers
// ---------------------------------------------------------------------------
__device__ __forceinline__ unsigned tf32r(float x) {
    unsigned r;
    asm("cvt.rna.tf32.f32 %0, %1;" : "=r"(r) : "f"(x));
    return r;
}

__device__ __forceinline__ float tanha(float x) {
    float y;
    asm("tanh.approx.f32 %0, %1;" : "=f"(y) : "f"(x));
    return y;
}

__device__ __forceinline__ void mma_tf32(float d[4],
                                         unsigned a0, unsigned a1,
                                         unsigned a2, unsigned a3,
                                         unsigned b0, unsigned b1) {
    asm volatile(
        "mma.sync.aligned.m16n8k8.row.col.f32.tf32.tf32.f32 "
        "{%0,%1,%2,%3}, {%4,%5,%6,%7}, {%8,%9}, {%0,%1,%2,%3};"
        : "+f"(d[0]), "+f"(d[1]), "+f"(d[2]), "+f"(d[3])
        : "r"(a0), "r"(a1), "r"(a2), "r"(a3), "r"(b0), "r"(b1));
}

// ---------------------------------------------------------------------------
// K0: transpose 256x256 (w[y][x] -> wt[x][y]), grid (8,8,2), block (32,8)
// ---------------------------------------------------------------------------
__global__ void transpose256_kernel(const float* __restrict__ w1,
                                    const float* __restrict__ w2,
                                    float* __restrict__ w1t,
                                    float* __restrict__ w2t) {
    __shared__ float tile[32][33];
    const float* w  = blockIdx.z ? w2  : w1;
    float*       wt = blockIdx.z ? w2t : w1t;
    int x = blockIdx.x * 32 + threadIdx.x;
    int y = blockIdx.y * 32 + threadIdx.y;
#pragma unroll
    for (int dy = 0; dy < 32; dy += 8)
        tile[threadIdx.y + dy][threadIdx.x] = w[(y + dy) * 256 + x];
    __syncthreads();
    x = blockIdx.y * 32 + threadIdx.x;
    y = blockIdx.x * 32 + threadIdx.y;
#pragma unroll
    for (int dy = 0; dy < 32; dy += 8)
        wt[(y + dy) * 256 + x] = tile[threadIdx.x][threadIdx.y + dy];
}

// ---------------------------------------------------------------------------
// K1: dec_proj[b,i] = sum_k w2t[k,i] * dec[b,k]   (coalesced in i)
// ---------------------------------------------------------------------------
__global__ void decproj_kernel(const float* __restrict__ dec,
                               const float* __restrict__ w2t,
                               float* __restrict__ dp) {
    __shared__ float ds[ENC_DIM];
    const int b = blockIdx.x;
    const int i = threadIdx.x;
    ds[i] = dec[b * ENC_DIM + i];
    __syncthreads();
    float acc = 0.f;
#pragma unroll 8
    for (int k = 0; k < ENC_DIM; ++k)
        acc = fmaf(__ldg(w2t + k * INT_DIM + i), ds[k], acc);
    dp[b * INT_DIM + i] = acc;
}

// ---------------------------------------------------------------------------
// K2: scores via tf32 mma. Block = 128 rows x 256 hidden, K=256 in 4 chunks.
// 8 warps, warp w owns rows [16w, 16w+16), all 256 n (32 subtiles of 8).
// Epilogue: +dec_proj, tanh.approx, *v, intra-warp reduce -> scores (no atomics)
// ---------------------------------------------------------------------------
__global__ void __launch_bounds__(256, 1)
scores_mma_kernel(const float* __restrict__ enc,
                  const float* __restrict__ w1t,
                  const float* __restrict__ dp,
                  const float* __restrict__ v,
                  float* __restrict__ scores,
                  int T) {
    extern __shared__ unsigned sm[];
    unsigned* as = sm;                 // [MT][AP]  tf32 X tile
    unsigned* bs = sm + MT * AP;       // [KC][BP]  tf32 w1t chunk, bs[k][n]
    __shared__ float dps[INT_DIM], vs[INT_DIM];

    const int tid  = threadIdx.x;
    const int wid  = tid >> 5;
    const int lane = tid & 31;
    const int g    = lane >> 2;        // groupID
    const int t    = lane & 3;         // threadID-in-group
    const int m0   = wid * 16;
    const long long row0 = (long long)blockIdx.x * MT;
    const int b = (int)(row0 / T);

    dps[tid] = dp[b * INT_DIM + tid];
    vs[tid]  = __ldg(v + tid);

    float d[32][4];
#pragma unroll
    for (int j = 0; j < 32; ++j)
#pragma unroll
        for (int q = 0; q < 4; ++q) d[j][q] = 0.f;

    for (int kc = 0; kc < ENC_DIM; kc += KC) {
        __syncthreads();
        // stage A: as[r][k] = tf32(enc[row0+r][kc+k]), coalesced
        const float* src = enc + row0 * ENC_DIM + kc;
#pragma unroll
        for (int idx = tid; idx < MT * KC; idx += 256) {
            int r = idx >> 6, k = idx & (KC - 1);
            as[r * AP + k] = tf32r(src[r * ENC_DIM + k]);
        }
        // stage B: bs[k][n] = tf32(w1t[kc+k][n]), coalesced
        const float* wsrc = w1t + kc * INT_DIM;
#pragma unroll
        for (int idx = tid; idx < KC * 256; idx += 256) {
            int k = idx >> 8, n = idx & 255;
            bs[k * BP + n] = tf32r(wsrc[k * INT_DIM + n]);
        }
        __syncthreads();

#pragma unroll
        for (int s = 0; s < KC / 8; ++s) {
            const int kk = s * 8;
            unsigned a0 = as[(m0 + g)     * AP + kk + t];
            unsigned a1 = as[(m0 + g + 8) * AP + kk + t];
            unsigned a2 = as[(m0 + g)     * AP + kk + t + 4];
            unsigned a3 = as[(m0 + g + 8) * AP + kk + t + 4];
            const unsigned* b0p = bs + (kk + t)     * BP + g;
            const unsigned* b1p = bs + (kk + t + 4) * BP + g;
#pragma unroll
            for (int j = 0; j < 32; ++j)
                mma_tf32(d[j], a0, a1, a2, a3, b0p[8 * j], b1p[8 * j]);
        }
    }

    // Epilogue: rows m0+g and m0+8+g; lane owns cols {8j+2t, 8j+2t+1}
    float s0 = 0.f, s1 = 0.f;
#pragma unroll
    for (int j = 0; j < 32; ++j) {
        const int n0 = 8 * j + 2 * t;
        const float vv0 = vs[n0],  vv1 = vs[n0 + 1];
        const float dd0 = dps[n0], dd1 = dps[n0 + 1];
        s0 += vv0 * tanha(d[j][0] + dd0) + vv1 * tanha(d[j][1] + dd1);
        s1 += vv0 * tanha(d[j][2] + dd0) + vv1 * tanha(d[j][3] + dd1);
    }
    s0 += __shfl_xor_sync(0xffffffffu, s0, 1);
    s0 += __shfl_xor_sync(0xffffffffu, s0, 2);
    s1 += __shfl_xor_sync(0xffffffffu, s1, 1);
    s1 += __shfl_xor_sync(0xffffffffu, s1, 2);
    if (t == 0) {
        scores[row0 + m0 + g]     = s0;
        scores[row0 + m0 + 8 + g] = s1;
    }
}

// ---------------------------------------------------------------------------
// K3: per-batch softmax over T -> probs (out[B*256 ..])
// ---------------------------------------------------------------------------
__global__ void softmax_kernel(const float* __restrict__ scores,
                               float* __restrict__ out,
                               int B, int T) {
    extern __shared__ float ss[];          // T floats
    __shared__ float red[8];
    const int b = blockIdx.x;
    const int tid = threadIdx.x;
    const int lane = tid & 31, wid = tid >> 5;

    for (int t = tid; t < T; t += 256) ss[t] = scores[b * T + t];
    __syncthreads();

    float m = -CUDART_INF_F;
    for (int t = tid; t < T; t += 256) m = fmaxf(m, ss[t]);
#pragma unroll
    for (int o = 16; o; o >>= 1) m = fmaxf(m, __shfl_xor_sync(0xffffffffu, m, o));
    if (lane == 0) red[wid] = m;
    __syncthreads();
    if (tid == 0) {
        float mm = red[0];
#pragma unroll
        for (int w = 1; w < 8; ++w) mm = fmaxf(mm, red[w]);
        red[0] = mm;
    }
    __syncthreads();
    m = red[0];
    __syncthreads();

    float z = 0.f;
    for (int t = tid; t < T; t += 256) z += expf(ss[t] - m);
#pragma unroll
    for (int o = 16; o; o >>= 1) z += __shfl_xor_sync(0xffffffffu, z, o);
    if (lane == 0) red[wid] = z;
    __syncthreads();
    if (tid == 0) {
        float zz = 0.f;
#pragma unroll
        for (int w = 0; w < 8; ++w) zz += red[w];
        red[0] = zz;
    }
    __syncthreads();
    const float inv = 1.f / red[0];

    float* probs = out + (long long)B * ENC_DIM;
    for (int t = tid; t < T; t += 256)
        probs[(long long)b * T + t] = expf(ss[t] - m) * inv;
}

// ---------------------------------------------------------------------------
// K4: context partials. grid (B, T/256). chunk c covers t in [256c, 256c+256).
// part[c][b][e] = sum_t p[t] * enc[b][t][e]
// ---------------------------------------------------------------------------
__global__ void ctx_partial_kernel(const float* __restrict__ enc,
                                   const float* __restrict__ out_probs,
                                   float* __restrict__ part,
                                   int B, int T) {
    __shared__ float ps[256];
    const int b = blockIdx.x;
    const int c = blockIdx.y;
    const int tid = threadIdx.x;
    const long long t0 = (long long)c * 256;

    ps[tid] = out_probs[(long long)b * T + t0 + tid];
    __syncthreads();

    float acc = 0.f;
    const float* e = enc + ((long long)b * T + t0) * ENC_DIM + tid;
#pragma unroll 8
    for (int t = 0; t < 256; ++t)
        acc = fmaf(ps[t], __ldg(e + (long long)t * ENC_DIM), acc);
    part[((long long)c * B + b) * ENC_DIM + tid] = acc;
}

// ---------------------------------------------------------------------------
// K5: reduce partials -> out context region
// ---------------------------------------------------------------------------
__global__ void ctx_reduce_kernel(const float* __restrict__ part,
                                  float* __restrict__ out,
                                  int B, int NC) {
    const int b = blockIdx.x;
    const int tid = threadIdx.x;
    float acc = 0.f;
    for (int c = 0; c < NC; ++c)
        acc += part[((long long)c * B + b) * ENC_DIM + tid];
    out[b * ENC_DIM + tid] = acc;
}

// ---------------------------------------------------------------------------
extern "C" void kernel_launch(void* const* d_in, const int* in_sizes, int n_in,
                              void* d_out, int out_size) {
    const float* enc = (const float*)d_in[0];   // [B,T,256]
    const float* dec = (const float*)d_in[1];   // [B,256]
    const float* w1  = (const float*)d_in[2];   // [256,256]
    const float* w2  = (const float*)d_in[3];   // [256,256]
    const float* v   = (const float*)d_in[4];   // [1,256]
    float* out = (float*)d_out;

    const int B = in_sizes[1] / ENC_DIM;                 // 64
    const int T = in_sizes[0] / (B * ENC_DIM);           // 2048
    const int NC = T / 256;                              // 8

    float* dp_ptr;      cudaGetSymbolAddress((void**)&dp_ptr, g_dp);
    float* scores_ptr;  cudaGetSymbolAddress((void**)&scores_ptr, g_scores);
    float* w1t_ptr;     cudaGetSymbolAddress((void**)&w1t_ptr, g_w1t);
    float* w2t_ptr;     cudaGetSymbolAddress((void**)&w2t_ptr, g_w2t);
    float* part_ptr;    cudaGetSymbolAddress((void**)&part_ptr, g_part);

    static const int sm_bytes = (MT * AP + KC * BP) * (int)sizeof(unsigned); // 102400
    cudaFuncSetAttribute(scores_mma_kernel,
                         cudaFuncAttributeMaxDynamicSharedMemorySize, sm_bytes);

    transpose256_kernel<<<dim3(8, 8, 2), dim3(32, 8)>>>(w1, w2, w1t_ptr, w2t_ptr);
    decproj_kernel<<<B, 256>>>(dec, w2t_ptr, dp_ptr);
    scores_mma_kernel<<<(B * T) / MT, 256, sm_bytes>>>(enc, w1t_ptr, dp_ptr, v,
                                                       scores_ptr, T);
    softmax_kernel<<<B, 256, T * (int)sizeof(float)>>>(scores_ptr, out, B, T);
    ctx_partial_kernel<<<dim3(B, NC), 256>>>(enc, out + (long long)B * ENC_DIM,
                                             part_ptr, B, T);
    ctx_reduce_kernel<<<B, 256>>>(part_ptr, out, B, NC);
}

// round 4
// speedup vs baseline: 16.1372x; 1.2147x over previous
#include <cuda_runtime.h>
#include <cuda_bf16.h>
#include <math_constants.h>

#define ENC_DIM 256
#define INT_DIM 256
#define MT 128            // rows per block in scores kernel
#define KC 32             // k-chunk staged per pipeline stage
#define AP 36             // A smem pitch (words): banks (4g+t) unique
#define BP 264            // B smem pitch (words): banks (8t+g) unique
#define ASZ (MT * AP)     // 4608 words
#define BSZ (KC * BP)     // 8448 words
#define NCHUNK (ENC_DIM / KC)   // 8
#define NC 16             // context chunks per batch

// Scratch (allocation-free rule: __device__ globals)
__device__ float g_dp[64 * INT_DIM];           // dec_proj [B, I]
__device__ float g_scores[64 * 2048];          // scores   [B, T]
__device__ float g_w1t[ENC_DIM * INT_DIM];     // w1 transposed + tf32-rounded
__device__ float g_w2t[ENC_DIM * INT_DIM];     // w2 transposed (full fp32)
__device__ float g_part[NC * 64 * ENC_DIM];    // context partials [chunk][B][E]

// ---------------------------------------------------------------------------
// helpers
// ---------------------------------------------------------------------------
__device__ __forceinline__ unsigned tf32r(float x) {
    unsigned r;
    asm("cvt.rna.tf32.f32 %0, %1;" : "=r"(r) : "f"(x));
    return r;
}

__device__ __forceinline__ float tanha(float x) {
    float y;
    asm("tanh.approx.f32 %0, %1;" : "=f"(y) : "f"(x));
    return y;
}

__device__ __forceinline__ void mma_tf32(float d[4],
                                         unsigned a0, unsigned a1,
                                         unsigned a2, unsigned a3,
                                         unsigned b0, unsigned b1) {
    asm volatile(
        "mma.sync.aligned.m16n8k8.row.col.f32.tf32.tf32.f32 "
        "{%0,%1,%2,%3}, {%4,%5,%6,%7}, {%8,%9}, {%0,%1,%2,%3};"
        : "+f"(d[0]), "+f"(d[1]), "+f"(d[2]), "+f"(d[3])
        : "r"(a0), "r"(a1), "r"(a2), "r"(a3), "r"(b0), "r"(b1));
}

__device__ __forceinline__ void cp16(unsigned dst_s, const void* src) {
    asm volatile("cp.async.cg.shared.global [%0], [%1], 16;"
                 :: "r"(dst_s), "l"(src) : "memory");
}
__device__ __forceinline__ void cp_commit() {
    asm volatile("cp.async.commit_group;" ::: "memory");
}
template <int N>
__device__ __forceinline__ void cp_wait() {
    asm volatile("cp.async.wait_group %0;" :: "n"(N) : "memory");
}

// ---------------------------------------------------------------------------
// K0: transpose 256x256. w1t gets tf32-rounded values (consumed only by mma);
// w2t stays full fp32 (consumed by decproj).
// ---------------------------------------------------------------------------
__global__ void transpose256_kernel(const float* __restrict__ w1,
                                    const float* __restrict__ w2,
                                    float* __restrict__ w1t,
                                    float* __restrict__ w2t) {
    __shared__ float tile[32][33];
    const bool second = blockIdx.z != 0;
    const float* w  = second ? w2  : w1;
    float*       wt = second ? w2t : w1t;
    int x = blockIdx.x * 32 + threadIdx.x;
    int y = blockIdx.y * 32 + threadIdx.y;
#pragma unroll
    for (int dy = 0; dy < 32; dy += 8)
        tile[threadIdx.y + dy][threadIdx.x] = w[(y + dy) * 256 + x];
    __syncthreads();
    x = blockIdx.y * 32 + threadIdx.x;
    y = blockIdx.x * 32 + threadIdx.y;
#pragma unroll
    for (int dy = 0; dy < 32; dy += 8) {
        float val = tile[threadIdx.x][threadIdx.y + dy];
        if (!second) val = __uint_as_float(tf32r(val));
        wt[(y + dy) * 256 + x] = val;
    }
}

// ---------------------------------------------------------------------------
// K1: dec_proj[b,i] = sum_k w2t[k,i] * dec[b,k]
// ---------------------------------------------------------------------------
__global__ void decproj_kernel(const float* __restrict__ dec,
                               const float* __restrict__ w2t,
                               float* __restrict__ dp) {
    __shared__ float ds[ENC_DIM];
    const int b = blockIdx.x;
    const int i = threadIdx.x;
    ds[i] = dec[b * ENC_DIM + i];
    __syncthreads();
    float acc = 0.f;
#pragma unroll 8
    for (int k = 0; k < ENC_DIM; ++k)
        acc = fmaf(__ldg(w2t + k * INT_DIM + i), ds[k], acc);
    dp[b * INT_DIM + i] = acc;
}

// ---------------------------------------------------------------------------
// K2: scores via tf32 mma, cp.async double-buffered.
// Block = 128 rows x 256 n. 8 warps: warp w -> rows [(w&3)*32, +32) (2 m-tiles),
// n-half nb = (w>>2)*128 (16 j-subtiles). B frag reused across the 2 m-tiles.
// ---------------------------------------------------------------------------
__global__ void __launch_bounds__(256, 1)
scores_mma_kernel(const float* __restrict__ enc,
                  const float* __restrict__ w1t,
                  const float* __restrict__ dp,
                  const float* __restrict__ v,
                  float* __restrict__ scores,
                  int T) {
    extern __shared__ unsigned sm[];
    // layout: A0 | A1 | B0 | B1
    __shared__ float dps[INT_DIM], vs[INT_DIM], ssc[MT];

    const int tid  = threadIdx.x;
    const int wid  = tid >> 5;
    const int lane = tid & 31;
    const int g    = lane >> 2;
    const int t    = lane & 3;
    const int m0   = (wid & 3) * 32;
    const int nb   = (wid >> 2) * 128;
    const long long row0 = (long long)blockIdx.x * MT;
    const int b = (int)(row0 / T);

    dps[tid] = dp[b * INT_DIM + tid];
    vs[tid]  = __ldg(v + tid);
    if (tid < MT) ssc[tid] = 0.f;

    const unsigned smem_base = (unsigned)__cvta_generic_to_shared(sm);

    // stage chunk c into buffer p = c&1
    auto stage = [&](int c) {
        const int p = c & 1;
        const int kc = c * KC;
        const unsigned abuf = smem_base + p * ASZ * 4;
        const unsigned bbuf = smem_base + (2 * ASZ + p * BSZ) * 4;
        // A: 128 rows x 32 floats = 1024 x 16B quads
#pragma unroll
        for (int i = tid; i < MT * 8; i += 256) {
            int r = i >> 3, q = i & 7;
            cp16(abuf + (r * AP + q * 4) * 4,
                 enc + (row0 + r) * ENC_DIM + kc + q * 4);
        }
        // B: 32 rows x 256 floats = 2048 x 16B quads
#pragma unroll
        for (int i = tid; i < KC * 64; i += 256) {
            int kr = i >> 6, q = i & 63;
            cp16(bbuf + (kr * BP + q * 4) * 4,
                 w1t + (kc + kr) * INT_DIM + q * 4);
        }
    };

    float d[2][16][4];
#pragma unroll
    for (int h = 0; h < 2; ++h)
#pragma unroll
        for (int j = 0; j < 16; ++j)
#pragma unroll
            for (int q = 0; q < 4; ++q) d[h][j][q] = 0.f;

    stage(0);
    cp_commit();

    for (int c = 0; c < NCHUNK; ++c) {
        if (c + 1 < NCHUNK) { stage(c + 1); cp_commit(); }
        if (c + 1 < NCHUNK) cp_wait<1>(); else cp_wait<0>();
        __syncthreads();

        const int p = c & 1;
        const unsigned* as = sm + p * ASZ;
        const unsigned* bs = sm + 2 * ASZ + p * BSZ;

#pragma unroll
        for (int s = 0; s < KC / 8; ++s) {
            const int kk = s * 8;
            unsigned a[2][4];
#pragma unroll
            for (int h = 0; h < 2; ++h) {
                const int r = m0 + 16 * h + g;
                a[h][0] = as[r * AP + kk + t];
                a[h][1] = as[(r + 8) * AP + kk + t];
                a[h][2] = as[r * AP + kk + t + 4];
                a[h][3] = as[(r + 8) * AP + kk + t + 4];
            }
            const unsigned* b0p = bs + (kk + t) * BP + nb + g;
            const unsigned* b1p = bs + (kk + t + 4) * BP + nb + g;
#pragma unroll
            for (int j = 0; j < 16; ++j) {
                unsigned b0 = b0p[8 * j], b1 = b1p[8 * j];
                mma_tf32(d[0][j], a[0][0], a[0][1], a[0][2], a[0][3], b0, b1);
                mma_tf32(d[1][j], a[1][0], a[1][1], a[1][2], a[1][3], b0, b1);
            }
        }
        __syncthreads();
    }

    // Epilogue: +dec_proj, tanh.approx, *v, reduce n within warp, combine the
    // two n-half warps via smem atomics (2-way).
#pragma unroll
    for (int h = 0; h < 2; ++h) {
        float s0 = 0.f, s1 = 0.f;
#pragma unroll
        for (int j = 0; j < 16; ++j) {
            const int n0 = nb + 8 * j + 2 * t;
            const float vv0 = vs[n0],  vv1 = vs[n0 + 1];
            const float dd0 = dps[n0], dd1 = dps[n0 + 1];
            s0 += vv0 * tanha(d[h][j][0] + dd0) + vv1 * tanha(d[h][j][1] + dd1);
            s1 += vv0 * tanha(d[h][j][2] + dd0) + vv1 * tanha(d[h][j][3] + dd1);
        }
        s0 += __shfl_xor_sync(0xffffffffu, s0, 1);
        s0 += __shfl_xor_sync(0xffffffffu, s0, 2);
        s1 += __shfl_xor_sync(0xffffffffu, s1, 1);
        s1 += __shfl_xor_sync(0xffffffffu, s1, 2);
        if (t == 0) {
            atomicAdd(&ssc[m0 + 16 * h + g], s0);
            atomicAdd(&ssc[m0 + 16 * h + 8 + g], s1);
        }
    }
    __syncthreads();
    if (tid < MT) scores[row0 + tid] = ssc[tid];
}

// ---------------------------------------------------------------------------
// K3: per-batch softmax over T -> probs (out[B*256 ..])
// ---------------------------------------------------------------------------
__global__ void softmax_kernel(const float* __restrict__ scores,
                               float* __restrict__ out,
                               int B, int T) {
    extern __shared__ float ss[];
    __shared__ float red[8];
    const int b = blockIdx.x;
    const int tid = threadIdx.x;
    const int lane = tid & 31, wid = tid >> 5;

    for (int t = tid; t < T; t += 256) ss[t] = scores[b * T + t];
    __syncthreads();

    float m = -CUDART_INF_F;
    for (int t = tid; t < T; t += 256) m = fmaxf(m, ss[t]);
#pragma unroll
    for (int o = 16; o; o >>= 1) m = fmaxf(m, __shfl_xor_sync(0xffffffffu, m, o));
    if (lane == 0) red[wid] = m;
    __syncthreads();
    if (tid == 0) {
        float mm = red[0];
#pragma unroll
        for (int w = 1; w < 8; ++w) mm = fmaxf(mm, red[w]);
        red[0] = mm;
    }
    __syncthreads();
    m = red[0];
    __syncthreads();

    float z = 0.f;
    for (int t = tid; t < T; t += 256) z += expf(ss[t] - m);
#pragma unroll
    for (int o = 16; o; o >>= 1) z += __shfl_xor_sync(0xffffffffu, z, o);
    if (lane == 0) red[wid] = z;
    __syncthreads();
    if (tid == 0) {
        float zz = 0.f;
#pragma unroll
        for (int w = 0; w < 8; ++w) zz += red[w];
        red[0] = zz;
    }
    __syncthreads();
    const float inv = 1.f / red[0];

    float* probs = out + (long long)B * ENC_DIM;
    for (int t = tid; t < T; t += 256)
        probs[(long long)b * T + t] = expf(ss[t] - m) * inv;
}

// ---------------------------------------------------------------------------
// K4: context partials. grid (B, NC). chunk covers T/NC timesteps.
// 4 independent accumulators for MLP.
// ---------------------------------------------------------------------------
__global__ void ctx_partial_kernel(const float* __restrict__ enc,
                                   const float* __restrict__ out_probs,
                                   float* __restrict__ part,
                                   int B, int T) {
    __shared__ float ps[2048 / NC];
    const int b = blockIdx.x;
    const int c = blockIdx.y;
    const int tid = threadIdx.x;
    const int TC = T / NC;                       // 128
    const long long t0 = (long long)c * TC;

    if (tid < TC) ps[tid] = out_probs[(long long)b * T + t0 + tid];
    __syncthreads();

    float a0 = 0.f, a1 = 0.f, a2 = 0.f, a3 = 0.f;
    const float* e = enc + ((long long)b * T + t0) * ENC_DIM + tid;
#pragma unroll 8
    for (int t = 0; t < TC; t += 4) {
        a0 = fmaf(ps[t],     __ldg(e + (long long)t * ENC_DIM),       a0);
        a1 = fmaf(ps[t + 1], __ldg(e + (long long)(t + 1) * ENC_DIM), a1);
        a2 = fmaf(ps[t + 2], __ldg(e + (long long)(t + 2) * ENC_DIM), a2);
        a3 = fmaf(ps[t + 3], __ldg(e + (long long)(t + 3) * ENC_DIM), a3);
    }
    part[((long long)c * B + b) * ENC_DIM + tid] = (a0 + a1) + (a2 + a3);
}

// ---------------------------------------------------------------------------
// K5: reduce partials -> out context region
// ---------------------------------------------------------------------------
__global__ void ctx_reduce_kernel(const float* __restrict__ part,
                                  float* __restrict__ out, int B) {
    const int b = blockIdx.x;
    const int tid = threadIdx.x;
    float acc = 0.f;
#pragma unroll
    for (int c = 0; c < NC; ++c)
        acc += part[((long long)c * B + b) * ENC_DIM + tid];
    out[b * ENC_DIM + tid] = acc;
}

// ---------------------------------------------------------------------------
extern "C" void kernel_launch(void* const* d_in, const int* in_sizes, int n_in,
                              void* d_out, int out_size) {
    const float* enc = (const float*)d_in[0];   // [B,T,256]
    const float* dec = (const float*)d_in[1];   // [B,256]
    const float* w1  = (const float*)d_in[2];   // [256,256]
    const float* w2  = (const float*)d_in[3];   // [256,256]
    const float* v   = (const float*)d_in[4];   // [1,256]
    float* out = (float*)d_out;

    const int B = in_sizes[1] / ENC_DIM;                 // 64
    const int T = in_sizes[0] / (B * ENC_DIM);           // 2048

    float* dp_ptr;      cudaGetSymbolAddress((void**)&dp_ptr, g_dp);
    float* scores_ptr;  cudaGetSymbolAddress((void**)&scores_ptr, g_scores);
    float* w1t_ptr;     cudaGetSymbolAddress((void**)&w1t_ptr, g_w1t);
    float* w2t_ptr;     cudaGetSymbolAddress((void**)&w2t_ptr, g_w2t);
    float* part_ptr;    cudaGetSymbolAddress((void**)&part_ptr, g_part);

    static const int sm_bytes = 2 * (ASZ + BSZ) * (int)sizeof(unsigned); // 104448
    cudaFuncSetAttribute(scores_mma_kernel,
                         cudaFuncAttributeMaxDynamicSharedMemorySize, sm_bytes);

    transpose256_kernel<<<dim3(8, 8, 2), dim3(32, 8)>>>(w1, w2, w1t_ptr, w2t_ptr);
    decproj_kernel<<<B, 256>>>(dec, w2t_ptr, dp_ptr);
    scores_mma_kernel<<<(B * T) / MT, 256, sm_bytes>>>(enc, w1t_ptr, dp_ptr, v,
                                                       scores_ptr, T);
    softmax_kernel<<<B, 256, T * (int)sizeof(float)>>>(scores_ptr, out, B, T);
    ctx_partial_kernel<<<dim3(B, NC), 256>>>(enc, out + (long long)B * ENC_DIM,
                                             part_ptr, B, T);
    ctx_reduce_kernel<<<B, 256>>>(part_ptr, out, B);
}

// round 6
// speedup vs baseline: 19.4116x; 1.2029x over previous
#include <cuda_runtime.h>
#include <cuda_fp16.h>
#include <cuda_bf16.h>
#include <math_constants.h>
#include <cstdint>

#define ENC_DIM 256
#define INT_DIM 256
#define MT 128                  // rows per CTA (M)
#define NT 256                  // hidden per CTA (N)
#define KC 32                   // k per staged chunk
#define NCHUNK (ENC_DIM / KC)   // 8
#define AP2 20                  // A smem pitch in u32 words (16 used + 4 pad)
#define BP2 20                  // B smem pitch in u32 words
#define ASZ2 (MT * AP2)         // 2560 words
#define BSZ2 (NT * BP2)         // 5120 words
#define DYN_BYTES (2 * (ASZ2 + BSZ2) * 4)   // 61440
#define NC 16                   // context chunks per batch

// Scratch (allocation-free rule: __device__ globals)
__device__ float  g_dp[64 * INT_DIM];          // dec_proj [B, I]
__device__ float  g_scores[64 * 2048];         // scores   [B, T]
__device__ float  g_w2t[ENC_DIM * INT_DIM];    // w2 transposed
__device__ __half g_w1h[INT_DIM * ENC_DIM];    // w1 as fp16, [n][k]
__device__ float  g_part[NC * 64 * ENC_DIM];   // context partials

// ---------------------------------------------------------------------------
// helpers
// ---------------------------------------------------------------------------
__device__ __forceinline__ float tanha(float x) {
    float y;
    asm("tanh.approx.f32 %0, %1;" : "=f"(y) : "f"(x));
    return y;
}
__device__ __forceinline__ void cp16(unsigned dst_s, const void* src) {
    asm volatile("cp.async.cg.shared.global [%0], [%1], 16;"
                 :: "r"(dst_s), "l"(src) : "memory");
}
__device__ __forceinline__ void cp_commit() {
    asm volatile("cp.async.commit_group;" ::: "memory");
}
template <int N>
__device__ __forceinline__ void cp_wait() {
    asm volatile("cp.async.wait_group %0;" :: "n"(N) : "memory");
}
__device__ __forceinline__ unsigned s2u(const void* p) {
    return (unsigned)__cvta_generic_to_shared(p);
}
__device__ __forceinline__ void mma_f16(float d[4], const unsigned a[4],
                                        unsigned b0, unsigned b1) {
    asm volatile(
        "mma.sync.aligned.m16n8k16.row.col.f32.f16.f16.f32 "
        "{%0,%1,%2,%3}, {%4,%5,%6,%7}, {%8,%9}, {%0,%1,%2,%3};"
        : "+f"(d[0]), "+f"(d[1]), "+f"(d[2]), "+f"(d[3])
        : "r"(a[0]), "r"(a[1]), "r"(a[2]), "r"(a[3]), "r"(b0), "r"(b1));
}

// ---------------------------------------------------------------------------
// K0a: w1 -> fp16 (layout unchanged: [n][k])
// ---------------------------------------------------------------------------
__global__ void w1half_kernel(const float* __restrict__ w1,
                              __half* __restrict__ w1h) {
    const int i = blockIdx.x * 256 + threadIdx.x;
    w1h[i] = __float2half(w1[i]);
}

// ---------------------------------------------------------------------------
// K0b: transpose w2 (for decproj coalescing)
// ---------------------------------------------------------------------------
__global__ void transpose_w2_kernel(const float* __restrict__ w2,
                                    float* __restrict__ w2t) {
    __shared__ float tile[32][33];
    int x = blockIdx.x * 32 + threadIdx.x;
    int y = blockIdx.y * 32 + threadIdx.y;
#pragma unroll
    for (int dy = 0; dy < 32; dy += 8)
        tile[threadIdx.y + dy][threadIdx.x] = w2[(y + dy) * 256 + x];
    __syncthreads();
    x = blockIdx.y * 32 + threadIdx.x;
    y = blockIdx.x * 32 + threadIdx.y;
#pragma unroll
    for (int dy = 0; dy < 32; dy += 8)
        w2t[(y + dy) * 256 + x] = tile[threadIdx.x][threadIdx.y + dy];
}

// ---------------------------------------------------------------------------
// K1: dec_proj[b,i] = sum_k w2t[k,i] * dec[b,k]
// ---------------------------------------------------------------------------
__global__ void decproj_kernel(const float* __restrict__ dec,
                               const float* __restrict__ w2t,
                               float* __restrict__ dp) {
    __shared__ float ds[ENC_DIM];
    const int b = blockIdx.x;
    const int i = threadIdx.x;
    ds[i] = dec[b * ENC_DIM + i];
    __syncthreads();
    float acc = 0.f;
#pragma unroll 8
    for (int k = 0; k < ENC_DIM; ++k)
        acc = fmaf(__ldg(w2t + k * INT_DIM + i), ds[k], acc);
    dp[b * INT_DIM + i] = acc;
}

// ---------------------------------------------------------------------------
// K2: scores via fp16 mma m16n8k16 (2x MACs/instr vs tf32 k8).
// Block = 128 rows x 256 n, K=256 in 8 chunks.
// A: LDG fp32 -> cvt fp16x2 -> STS (register-pipelined). B: cp.async of g_w1h.
// Warp w: rows [(w&3)*32, +32) (2 m-tiles), n-half (w>>2)*128 (16 j-subtiles).
// ---------------------------------------------------------------------------
__global__ void __launch_bounds__(256, 1)
scores_mma_kernel(const float* __restrict__ enc,
                  const __half* __restrict__ w1h,
                  const float* __restrict__ dp,
                  const float* __restrict__ v,
                  float* __restrict__ scores,
                  int T) {
    extern __shared__ unsigned sm[];          // A0 | A1 | B0 | B1
    __shared__ float dps[INT_DIM], vs[INT_DIM], ssc[MT];

    const int tid  = threadIdx.x;
    const int wid  = tid >> 5;
    const int lane = tid & 31;
    const int g    = lane >> 2;
    const int t    = lane & 3;
    const int m0   = (wid & 3) * 32;
    const int nb   = (wid >> 2) * 128;
    const long long row0 = (long long)blockIdx.x * MT;
    const int b = (int)(row0 / T);

    dps[tid] = dp[b * INT_DIM + tid];
    vs[tid]  = __ldg(v + tid);
    if (tid < MT) ssc[tid] = 0.f;

    const unsigned smem_base = s2u(sm);
    const int ar = tid >> 1;                  // A staging: row
    const int ah = tid & 1;                   // A staging: half-row

    // stage B chunk c (fp16 pairs) into buffer c&1 via cp.async
    auto stageB = [&](int c) {
        const int kc = c * KC;
        const unsigned bb = smem_base + (2 * ASZ2 + (c & 1) * BSZ2) * 4;
#pragma unroll
        for (int i = tid; i < NT * 4; i += 256) {     // 1024 cp16
            int n = i >> 2, q = i & 3;
            cp16(bb + (n * BP2 + q * 4) * 4, w1h + n * ENC_DIM + kc + q * 8);
        }
    };

    float4 fr[4];                              // A prefetch regs (16 floats)
    auto ldgA = [&](int c) {
        const float4* src = reinterpret_cast<const float4*>(
            enc + (row0 + ar) * ENC_DIM + c * KC + ah * 16);
        fr[0] = src[0]; fr[1] = src[1]; fr[2] = src[2]; fr[3] = src[3];
    };
    auto stsA = [&](int c) {
        uint32_t w[8];
#pragma unroll
        for (int q = 0; q < 4; ++q) {
            __half2 h0 = __floats2half2_rn(fr[q].x, fr[q].y);
            __half2 h1 = __floats2half2_rn(fr[q].z, fr[q].w);
            w[2 * q]     = *reinterpret_cast<uint32_t*>(&h0);
            w[2 * q + 1] = *reinterpret_cast<uint32_t*>(&h1);
        }
        uint4* dst = reinterpret_cast<uint4*>(
            sm + (c & 1) * ASZ2 + ar * AP2 + ah * 8);
        dst[0] = make_uint4(w[0], w[1], w[2], w[3]);
        dst[1] = make_uint4(w[4], w[5], w[6], w[7]);
    };

    float d[2][16][4];
#pragma unroll
    for (int h = 0; h < 2; ++h)
#pragma unroll
        for (int j = 0; j < 16; ++j)
#pragma unroll
            for (int q = 0; q < 4; ++q) d[h][j][q] = 0.f;

    // prologue: B0,B1 in flight; A0 staged; regs hold A1
    stageB(0); cp_commit();
    stageB(1); cp_commit();
    ldgA(0);
    stsA(0);
    ldgA(1);
    cp_wait<1>();                              // B0 arrived
    __syncthreads();

    for (int c = 0; c < NCHUNK; ++c) {
        const int p = c & 1;
        const unsigned* as = sm + p * ASZ2;
        const unsigned* bs = sm + 2 * ASZ2 + p * BSZ2;

#pragma unroll
        for (int s = 0; s < 2; ++s) {          // two k16 steps per chunk
            unsigned a[2][4];
#pragma unroll
            for (int h = 0; h < 2; ++h) {
                const int r = m0 + 16 * h + g;
                a[h][0] = as[r * AP2 + s * 8 + t];
                a[h][1] = as[(r + 8) * AP2 + s * 8 + t];
                a[h][2] = as[r * AP2 + s * 8 + t + 4];
                a[h][3] = as[(r + 8) * AP2 + s * 8 + t + 4];
            }
            const unsigned* b0p = bs + (nb + g) * BP2 + s * 8 + t;
#pragma unroll
            for (int j = 0; j < 16; ++j) {
                unsigned b0 = b0p[8 * j * BP2];
                unsigned b1 = b0p[8 * j * BP2 + 4];
                mma_f16(d[0][j], a[0], b0, b1);
                mma_f16(d[1][j], a[1], b0, b1);
            }
        }

        if (c + 1 < NCHUNK) stsA(c + 1);       // regs from prev iter
        if (c + 2 < NCHUNK) {
            ldgA(c + 2);
            stageB(c + 2); cp_commit();
            cp_wait<1>();                      // B(c+1) arrived
        } else {
            cp_wait<0>();
        }
        __syncthreads();
    }

    // Epilogue: +dec_proj, tanh.approx, *v, warp-reduce n, 2-way smem combine
#pragma unroll
    for (int h = 0; h < 2; ++h) {
        float s0 = 0.f, s1 = 0.f;
#pragma unroll
        for (int j = 0; j < 16; ++j) {
            const int n0 = nb + 8 * j + 2 * t;
            const float vv0 = vs[n0],  vv1 = vs[n0 + 1];
            const float dd0 = dps[n0], dd1 = dps[n0 + 1];
            s0 += vv0 * tanha(d[h][j][0] + dd0) + vv1 * tanha(d[h][j][1] + dd1);
            s1 += vv0 * tanha(d[h][j][2] + dd0) + vv1 * tanha(d[h][j][3] + dd1);
        }
        s0 += __shfl_xor_sync(0xffffffffu, s0, 1);
        s0 += __shfl_xor_sync(0xffffffffu, s0, 2);
        s1 += __shfl_xor_sync(0xffffffffu, s1, 1);
        s1 += __shfl_xor_sync(0xffffffffu, s1, 2);
        if (t == 0) {
            atomicAdd(&ssc[m0 + 16 * h + g], s0);
            atomicAdd(&ssc[m0 + 16 * h + 8 + g], s1);
        }
    }
    __syncthreads();
    if (tid < MT) scores[row0 + tid] = ssc[tid];
}

// ---------------------------------------------------------------------------
// K3: per-batch softmax over T -> probs (out[B*256 ..])
// ---------------------------------------------------------------------------
__global__ void softmax_kernel(const float* __restrict__ scores,
                               float* __restrict__ out,
                               int B, int T) {
    extern __shared__ float ss[];
    __shared__ float red[8];
    const int b = blockIdx.x;
    const int tid = threadIdx.x;
    const int lane = tid & 31, wid = tid >> 5;

    for (int t = tid; t < T; t += 256) ss[t] = scores[b * T + t];
    __syncthreads();

    float m = -CUDART_INF_F;
    for (int t = tid; t < T; t += 256) m = fmaxf(m, ss[t]);
#pragma unroll
    for (int o = 16; o; o >>= 1) m = fmaxf(m, __shfl_xor_sync(0xffffffffu, m, o));
    if (lane == 0) red[wid] = m;
    __syncthreads();
    if (tid == 0) {
        float mm = red[0];
#pragma unroll
        for (int w = 1; w < 8; ++w) mm = fmaxf(mm, red[w]);
        red[0] = mm;
    }
    __syncthreads();
    m = red[0];
    __syncthreads();

    float z = 0.f;
    for (int t = tid; t < T; t += 256) z += expf(ss[t] - m);
#pragma unroll
    for (int o = 16; o; o >>= 1) z += __shfl_xor_sync(0xffffffffu, z, o);
    if (lane == 0) red[wid] = z;
    __syncthreads();
    if (tid == 0) {
        float zz = 0.f;
#pragma unroll
        for (int w = 0; w < 8; ++w) zz += red[w];
        red[0] = zz;
    }
    __syncthreads();
    const float inv = 1.f / red[0];

    float* probs = out + (long long)B * ENC_DIM;
    for (int t = tid; t < T; t += 256)
        probs[(long long)b * T + t] = expf(ss[t] - m) * inv;
}

// ---------------------------------------------------------------------------
// K4: context partials. grid (B, NC). 4 accumulators for MLP.
// ---------------------------------------------------------------------------
__global__ void ctx_partial_kernel(const float* __restrict__ enc,
                                   const float* __restrict__ out_probs,
                                   float* __restrict__ part,
                                   int B, int T) {
    __shared__ float ps[2048 / NC];
    const int b = blockIdx.x;
    const int c = blockIdx.y;
    const int tid = threadIdx.x;
    const int TC = T / NC;                       // 128
    const long long t0 = (long long)c * TC;

    if (tid < TC) ps[tid] = out_probs[(long long)b * T + t0 + tid];
    __syncthreads();

    float a0 = 0.f, a1 = 0.f, a2 = 0.f, a3 = 0.f;
    const float* e = enc + ((long long)b * T + t0) * ENC_DIM + tid;
#pragma unroll 8
    for (int t = 0; t < TC; t += 4) {
        a0 = fmaf(ps[t],     __ldg(e + (long long)t * ENC_DIM),       a0);
        a1 = fmaf(ps[t + 1], __ldg(e + (long long)(t + 1) * ENC_DIM), a1);
        a2 = fmaf(ps[t + 2], __ldg(e + (long long)(t + 2) * ENC_DIM), a2);
        a3 = fmaf(ps[t + 3], __ldg(e + (long long)(t + 3) * ENC_DIM), a3);
    }
    part[((long long)c * B + b) * ENC_DIM + tid] = (a0 + a1) + (a2 + a3);
}

// ---------------------------------------------------------------------------
// K5: reduce partials -> out context region
// ---------------------------------------------------------------------------
__global__ void ctx_reduce_kernel(const float* __restrict__ part,
                                  float* __restrict__ out, int B) {
    const int b = blockIdx.x;
    const int tid = threadIdx.x;
    float acc = 0.f;
#pragma unroll
    for (int c = 0; c < NC; ++c)
        acc += part[((long long)c * B + b) * ENC_DIM + tid];
    out[b * ENC_DIM + tid] = acc;
}

// ---------------------------------------------------------------------------
extern "C" void kernel_launch(void* const* d_in, const int* in_sizes, int n_in,
                              void* d_out, int out_size) {
    const float* enc = (const float*)d_in[0];   // [B,T,256]
    const float* dec = (const float*)d_in[1];   // [B,256]
    const float* w1  = (const float*)d_in[2];   // [256,256]
    const float* w2  = (const float*)d_in[3];   // [256,256]
    const float* v   = (const float*)d_in[4];   // [1,256]
    float* out = (float*)d_out;

    const int B = in_sizes[1] / ENC_DIM;                 // 64
    const int T = in_sizes[0] / (B * ENC_DIM);           // 2048

    float*  dp_ptr;     cudaGetSymbolAddress((void**)&dp_ptr, g_dp);
    float*  scores_ptr; cudaGetSymbolAddress((void**)&scores_ptr, g_scores);
    float*  w2t_ptr;    cudaGetSymbolAddress((void**)&w2t_ptr, g_w2t);
    __half* w1h_ptr;    cudaGetSymbolAddress((void**)&w1h_ptr, g_w1h);
    float*  part_ptr;   cudaGetSymbolAddress((void**)&part_ptr, g_part);

    cudaFuncSetAttribute(scores_mma_kernel,
                         cudaFuncAttributeMaxDynamicSharedMemorySize, DYN_BYTES);

    w1half_kernel<<<INT_DIM * ENC_DIM / 256, 256>>>(w1, w1h_ptr);
    transpose_w2_kernel<<<dim3(8, 8), dim3(32, 8)>>>(w2, w2t_ptr);
    decproj_kernel<<<B, 256>>>(dec, w2t_ptr, dp_ptr);
    scores_mma_kernel<<<(B * T) / MT, 256, DYN_BYTES>>>(enc, w1h_ptr, dp_ptr, v,
                                                        scores_ptr, T);
    softmax_kernel<<<B, 256, T * (int)sizeof(float)>>>(scores_ptr, out, B, T);
    ctx_partial_kernel<<<dim3(B, NC), 256>>>(enc, out + (long long)B * ENC_DIM,
                                             part_ptr, B, T);
    ctx_reduce_kernel<<<B, 256>>>(part_ptr, out, B);
}

// round 7
// speedup vs baseline: 19.9925x; 1.0299x over previous
#include <cuda_runtime.h>
#include <cuda_fp16.h>
#include <cuda_bf16.h>
#include <math_constants.h>
#include <cstdint>

#define ENC_DIM 256
#define INT_DIM 256
#define MT 128                  // rows per CTA (M)
#define NT 256                  // hidden per CTA (N)
#define KC 64                   // k per staged chunk
#define NCHUNK (ENC_DIM / KC)   // 4
#define NKS (KC / 16)           // 4 k16 steps per chunk
#define P 36                    // smem pitch in u32 words (32 used + 4 pad)
#define ASZ (MT * P)            // 4608 words
#define BSZ (NT * P)            // 9216 words
#define DYN_BYTES (2 * (ASZ + BSZ) * 4)   // 110592
#define NTHR 512
#define NC 16                   // context chunks per batch

// Scratch (allocation-free rule: __device__ globals)
__device__ float  g_dp[64 * INT_DIM];          // dec_proj [B, I]
__device__ float  g_scores[64 * 2048];         // scores   [B, T]
__device__ float  g_w2t[ENC_DIM * INT_DIM];    // w2 transposed
__device__ __half g_w1h[INT_DIM * ENC_DIM];    // w1 as fp16, [n][k]
__device__ float  g_part[NC * 64 * ENC_DIM];   // context partials

// ---------------------------------------------------------------------------
// helpers
// ---------------------------------------------------------------------------
__device__ __forceinline__ float tanha(float x) {
    float y;
    asm("tanh.approx.f32 %0, %1;" : "=f"(y) : "f"(x));
    return y;
}
__device__ __forceinline__ void cp16(unsigned dst_s, const void* src) {
    asm volatile("cp.async.cg.shared.global [%0], [%1], 16;"
                 :: "r"(dst_s), "l"(src) : "memory");
}
__device__ __forceinline__ void cp_commit() {
    asm volatile("cp.async.commit_group;" ::: "memory");
}
template <int N>
__device__ __forceinline__ void cp_wait() {
    asm volatile("cp.async.wait_group %0;" :: "n"(N) : "memory");
}
__device__ __forceinline__ unsigned s2u(const void* p) {
    return (unsigned)__cvta_generic_to_shared(p);
}
__device__ __forceinline__ void mma_f16(float d[4], const unsigned a[4],
                                        unsigned b0, unsigned b1) {
    asm volatile(
        "mma.sync.aligned.m16n8k16.row.col.f32.f16.f16.f32 "
        "{%0,%1,%2,%3}, {%4,%5,%6,%7}, {%8,%9}, {%0,%1,%2,%3};"
        : "+f"(d[0]), "+f"(d[1]), "+f"(d[2]), "+f"(d[3])
        : "r"(a[0]), "r"(a[1]), "r"(a[2]), "r"(a[3]), "r"(b0), "r"(b1));
}

// ---------------------------------------------------------------------------
// K0a: w1 -> fp16 (layout unchanged: [n][k])
// ---------------------------------------------------------------------------
__global__ void w1half_kernel(const float* __restrict__ w1,
                              __half* __restrict__ w1h) {
    const int i = blockIdx.x * 256 + threadIdx.x;
    w1h[i] = __float2half(w1[i]);
}

// ---------------------------------------------------------------------------
// K0b: transpose w2 (for decproj coalescing)
// ---------------------------------------------------------------------------
__global__ void transpose_w2_kernel(const float* __restrict__ w2,
                                    float* __restrict__ w2t) {
    __shared__ float tile[32][33];
    int x = blockIdx.x * 32 + threadIdx.x;
    int y = blockIdx.y * 32 + threadIdx.y;
#pragma unroll
    for (int dy = 0; dy < 32; dy += 8)
        tile[threadIdx.y + dy][threadIdx.x] = w2[(y + dy) * 256 + x];
    __syncthreads();
    x = blockIdx.y * 32 + threadIdx.x;
    y = blockIdx.x * 32 + threadIdx.y;
#pragma unroll
    for (int dy = 0; dy < 32; dy += 8)
        w2t[(y + dy) * 256 + x] = tile[threadIdx.x][threadIdx.y + dy];
}

// ---------------------------------------------------------------------------
// K1: dec_proj[b,i] = sum_k w2t[k,i] * dec[b,k]
// ---------------------------------------------------------------------------
__global__ void decproj_kernel(const float* __restrict__ dec,
                               const float* __restrict__ w2t,
                               float* __restrict__ dp) {
    __shared__ float ds[ENC_DIM];
    const int b = blockIdx.x;
    const int i = threadIdx.x;
    ds[i] = dec[b * ENC_DIM + i];
    __syncthreads();
    float acc = 0.f;
#pragma unroll 8
    for (int k = 0; k < ENC_DIM; ++k)
        acc = fmaf(__ldg(w2t + k * INT_DIM + i), ds[k], acc);
    dp[b * INT_DIM + i] = acc;
}

// ---------------------------------------------------------------------------
// K2: scores via fp16 mma m16n8k16, 512 threads (16 warps, 4/SMSP).
// Block = 128 rows x 256 n, K=256 in 4 chunks of 64.
// Warp w: m-group (w&3)*32 (2 m-tiles, B reused), n-quarter (w>>2)*64 (8 j).
// Accums: d[2][8][4] = 64 regs -> ~115 regs/thread, 16 warps/SM.
// ---------------------------------------------------------------------------
__global__ void __launch_bounds__(NTHR, 1)
scores_mma_kernel(const float* __restrict__ enc,
                  const __half* __restrict__ w1h,
                  const float* __restrict__ dp,
                  const float* __restrict__ v,
                  float* __restrict__ scores,
                  int T) {
    extern __shared__ unsigned sm[];          // A0 | A1 | B0 | B1
    __shared__ float dps[INT_DIM], vs[INT_DIM], ssc[MT];

    const int tid  = threadIdx.x;
    const int wid  = tid >> 5;
    const int lane = tid & 31;
    const int g    = lane >> 2;
    const int t    = lane & 3;
    const int m0   = (wid & 3) * 32;
    const int nb   = (wid >> 2) * 64;
    const long long row0 = (long long)blockIdx.x * MT;
    const int b = (int)(row0 / T);

    if (tid < INT_DIM) {
        dps[tid] = dp[b * INT_DIM + tid];
        vs[tid]  = __ldg(v + tid);
    }
    if (tid < MT) ssc[tid] = 0.f;

    const unsigned smem_base = s2u(sm);
    const int ar = tid >> 2;                  // A staging: row (0..127)
    const int aq = tid & 3;                   // A staging: quarter (16 floats)

    // stage B chunk c into buffer c&1 via cp.async (2048 cp16 / 512 thr = 4)
    auto stageB = [&](int c) {
        const int kc = c * KC;
        const unsigned bb = smem_base + (2 * ASZ + (c & 1) * BSZ) * 4;
#pragma unroll
        for (int i = tid; i < NT * 8; i += NTHR) {
            int n = i >> 3, q = i & 7;
            cp16(bb + (n * P + q * 4) * 4, w1h + n * ENC_DIM + kc + q * 8);
        }
    };

    float4 fr[4];                              // A prefetch regs (16 floats)
    auto ldgA = [&](int c) {
        const float4* src = reinterpret_cast<const float4*>(
            enc + (row0 + ar) * ENC_DIM + c * KC + aq * 16);
        fr[0] = src[0]; fr[1] = src[1]; fr[2] = src[2]; fr[3] = src[3];
    };
    auto stsA = [&](int c) {
        uint32_t w[8];
#pragma unroll
        for (int q = 0; q < 4; ++q) {
            __half2 h0 = __floats2half2_rn(fr[q].x, fr[q].y);
            __half2 h1 = __floats2half2_rn(fr[q].z, fr[q].w);
            w[2 * q]     = *reinterpret_cast<uint32_t*>(&h0);
            w[2 * q + 1] = *reinterpret_cast<uint32_t*>(&h1);
        }
        uint4* dst = reinterpret_cast<uint4*>(
            sm + (c & 1) * ASZ + ar * P + aq * 8);
        dst[0] = make_uint4(w[0], w[1], w[2], w[3]);
        dst[1] = make_uint4(w[4], w[5], w[6], w[7]);
    };

    float d[2][8][4];
#pragma unroll
    for (int h = 0; h < 2; ++h)
#pragma unroll
        for (int j = 0; j < 8; ++j)
#pragma unroll
            for (int q = 0; q < 4; ++q) d[h][j][q] = 0.f;

    // prologue: B0,B1 in flight; A0 staged; regs hold A1
    stageB(0); cp_commit();
    stageB(1); cp_commit();
    ldgA(0);
    stsA(0);
    ldgA(1);
    cp_wait<1>();                              // B0 arrived
    __syncthreads();

    for (int c = 0; c < NCHUNK; ++c) {
        const int p = c & 1;
        const unsigned* as = sm + p * ASZ;
        const unsigned* bs = sm + 2 * ASZ + p * BSZ;

#pragma unroll
        for (int s = 0; s < NKS; ++s) {        // four k16 steps per chunk
            unsigned a[2][4];
#pragma unroll
            for (int h = 0; h < 2; ++h) {
                const int r = m0 + 16 * h + g;
                a[h][0] = as[r * P + s * 8 + t];
                a[h][1] = as[(r + 8) * P + s * 8 + t];
                a[h][2] = as[r * P + s * 8 + t + 4];
                a[h][3] = as[(r + 8) * P + s * 8 + t + 4];
            }
            const unsigned* b0p = bs + (nb + g) * P + s * 8 + t;
#pragma unroll
            for (int j = 0; j < 8; ++j) {
                unsigned b0 = b0p[8 * j * P];
                unsigned b1 = b0p[8 * j * P + 4];
                mma_f16(d[0][j], a[0], b0, b1);
                mma_f16(d[1][j], a[1], b0, b1);
            }
        }

        if (c + 1 < NCHUNK) stsA(c + 1);       // writes buffer 1-p: safe
        __syncthreads();                        // chunk c fully consumed
        if (c + 2 < NCHUNK) {
            ldgA(c + 2);
            stageB(c + 2); cp_commit();        // writes buffer p: now safe
            cp_wait<1>();                      // B(c+1) arrived
        } else {
            cp_wait<0>();
        }
        __syncthreads();                        // staged data visible to all
    }

    // Epilogue: +dec_proj, tanh.approx, *v, warp-reduce n, 4-way smem combine
#pragma unroll
    for (int h = 0; h < 2; ++h) {
        float s0 = 0.f, s1 = 0.f;
#pragma unroll
        for (int j = 0; j < 8; ++j) {
            const int n0 = nb + 8 * j + 2 * t;
            const float vv0 = vs[n0],  vv1 = vs[n0 + 1];
            const float dd0 = dps[n0], dd1 = dps[n0 + 1];
            s0 += vv0 * tanha(d[h][j][0] + dd0) + vv1 * tanha(d[h][j][1] + dd1);
            s1 += vv0 * tanha(d[h][j][2] + dd0) + vv1 * tanha(d[h][j][3] + dd1);
        }
        s0 += __shfl_xor_sync(0xffffffffu, s0, 1);
        s0 += __shfl_xor_sync(0xffffffffu, s0, 2);
        s1 += __shfl_xor_sync(0xffffffffu, s1, 1);
        s1 += __shfl_xor_sync(0xffffffffu, s1, 2);
        if (t == 0) {
            atomicAdd(&ssc[m0 + 16 * h + g], s0);
            atomicAdd(&ssc[m0 + 16 * h + 8 + g], s1);
        }
    }
    __syncthreads();
    if (tid < MT) scores[row0 + tid] = ssc[tid];
}

// ---------------------------------------------------------------------------
// K3: per-batch softmax over T -> probs (out[B*256 ..])
// ---------------------------------------------------------------------------
__global__ void softmax_kernel(const float* __restrict__ scores,
                               float* __restrict__ out,
                               int B, int T) {
    extern __shared__ float ss[];
    __shared__ float red[8];
    const int b = blockIdx.x;
    const int tid = threadIdx.x;
    const int lane = tid & 31, wid = tid >> 5;

    for (int t = tid; t < T; t += 256) ss[t] = scores[b * T + t];
    __syncthreads();

    float m = -CUDART_INF_F;
    for (int t = tid; t < T; t += 256) m = fmaxf(m, ss[t]);
#pragma unroll
    for (int o = 16; o; o >>= 1) m = fmaxf(m, __shfl_xor_sync(0xffffffffu, m, o));
    if (lane == 0) red[wid] = m;
    __syncthreads();
    if (tid == 0) {
        float mm = red[0];
#pragma unroll
        for (int w = 1; w < 8; ++w) mm = fmaxf(mm, red[w]);
        red[0] = mm;
    }
    __syncthreads();
    m = red[0];
    __syncthreads();

    float z = 0.f;
    for (int t = tid; t < T; t += 256) z += expf(ss[t] - m);
#pragma unroll
    for (int o = 16; o; o >>= 1) z += __shfl_xor_sync(0xffffffffu, z, o);
    if (lane == 0) red[wid] = z;
    __syncthreads();
    if (tid == 0) {
        float zz = 0.f;
#pragma unroll
        for (int w = 0; w < 8; ++w) zz += red[w];
        red[0] = zz;
    }
    __syncthreads();
    const float inv = 1.f / red[0];

    float* probs = out + (long long)B * ENC_DIM;
    for (int t = tid; t < T; t += 256)
        probs[(long long)b * T + t] = expf(ss[t] - m) * inv;
}

// ---------------------------------------------------------------------------
// K4: context partials. grid (B, NC). 4 accumulators for MLP.
// ---------------------------------------------------------------------------
__global__ void ctx_partial_kernel(const float* __restrict__ enc,
                                   const float* __restrict__ out_probs,
                                   float* __restrict__ part,
                                   int B, int T) {
    __shared__ float ps[2048 / NC];
    const int b = blockIdx.x;
    const int c = blockIdx.y;
    const int tid = threadIdx.x;
    const int TC = T / NC;                       // 128
    const long long t0 = (long long)c * TC;

    if (tid < TC) ps[tid] = out_probs[(long long)b * T + t0 + tid];
    __syncthreads();

    float a0 = 0.f, a1 = 0.f, a2 = 0.f, a3 = 0.f;
    const float* e = enc + ((long long)b * T + t0) * ENC_DIM + tid;
#pragma unroll 8
    for (int t = 0; t < TC; t += 4) {
        a0 = fmaf(ps[t],     __ldg(e + (long long)t * ENC_DIM),       a0);
        a1 = fmaf(ps[t + 1], __ldg(e + (long long)(t + 1) * ENC_DIM), a1);
        a2 = fmaf(ps[t + 2], __ldg(e + (long long)(t + 2) * ENC_DIM), a2);
        a3 = fmaf(ps[t + 3], __ldg(e + (long long)(t + 3) * ENC_DIM), a3);
    }
    part[((long long)c * B + b) * ENC_DIM + tid] = (a0 + a1) + (a2 + a3);
}

// ---------------------------------------------------------------------------
// K5: reduce partials -> out context region
// ---------------------------------------------------------------------------
__global__ void ctx_reduce_kernel(const float* __restrict__ part,
                                  float* __restrict__ out, int B) {
    const int b = blockIdx.x;
    const int tid = threadIdx.x;
    float acc = 0.f;
#pragma unroll
    for (int c = 0; c < NC; ++c)
        acc += part[((long long)c * B + b) * ENC_DIM + tid];
    out[b * ENC_DIM + tid] = acc;
}

// ---------------------------------------------------------------------------
extern "C" void kernel_launch(void* const* d_in, const int* in_sizes, int n_in,
                              void* d_out, int out_size) {
    const float* enc = (const float*)d_in[0];   // [B,T,256]
    const float* dec = (const float*)d_in[1];   // [B,256]
    const float* w1  = (const float*)d_in[2];   // [256,256]
    const float* w2  = (const float*)d_in[3];   // [256,256]
    const float* v   = (const float*)d_in[4];   // [1,256]
    float* out = (float*)d_out;

    const int B = in_sizes[1] / ENC_DIM;                 // 64
    const int T = in_sizes[0] / (B * ENC_DIM);           // 2048

    float*  dp_ptr;     cudaGetSymbolAddress((void**)&dp_ptr, g_dp);
    float*  scores_ptr; cudaGetSymbolAddress((void**)&scores_ptr, g_scores);
    float*  w2t_ptr;    cudaGetSymbolAddress((void**)&w2t_ptr, g_w2t);
    __half* w1h_ptr;    cudaGetSymbolAddress((void**)&w1h_ptr, g_w1h);
    float*  part_ptr;   cudaGetSymbolAddress((void**)&part_ptr, g_part);

    cudaFuncSetAttribute(scores_mma_kernel,
                         cudaFuncAttributeMaxDynamicSharedMemorySize, DYN_BYTES);

    w1half_kernel<<<INT_DIM * ENC_DIM / 256, 256>>>(w1, w1h_ptr);
    transpose_w2_kernel<<<dim3(8, 8), dim3(32, 8)>>>(w2, w2t_ptr);
    decproj_kernel<<<B, 256>>>(dec, w2t_ptr, dp_ptr);
    scores_mma_kernel<<<(B * T) / MT, NTHR, DYN_BYTES>>>(enc, w1h_ptr, dp_ptr, v,
                                                         scores_ptr, T);
    softmax_kernel<<<B, 256, T * (int)sizeof(float)>>>(scores_ptr, out, B, T);
    ctx_partial_kernel<<<dim3(B, NC), 256>>>(enc, out + (long long)B * ENC_DIM,
                                             part_ptr, B, T);
    ctx_reduce_kernel<<<B, 256>>>(part_ptr, out, B);
}